// round 12
// baseline (speedup 1.0000x reference)
#include <cuda_runtime.h>
#include <cuda_bf16.h>

// SpatialTransformer: 3D trilinear grid-sample, border padding, align_corners=True.
// img [2,1,160,192,224], flow [2,3,160,192,224], out [2,1,160,192,224].
//
// px = (x+flow0+1)*111.5 clamps to 223 (fx=0) for essentially all x>=8 ->
// bilinear on the x=223 slice. R12: z-SLAB tiling. Each CTA owns 64 contiguous
// compact rows (z-span <= 2 planes) and caches slice planes [z_lo-8, z_hi+9]
// (<=19 planes x 197 floats = 15 KB smem). TPB=256, launch_bounds(256,5) ->
// 40 warps/SM (beats the 32-warp RF cap of the 123KB-slice design). Gaussian
// tails beyond the +-8 guard fall back to the global compact slice (identical
// values). Phase A: x in [8,224) warp-uniform fast path (4 LDS + 6 FFMA).
// Phase B: x in [0,8) mixed. SP=197 keeps the (z0,y0) patch on distinct banks.

#define DD 160
#define HH 192
#define WW 224
#define HW (HH * WW)
#define NVOX (DD * HH * WW)     // 6,881,280
#define NB 2
#define ROWS (DD * HH)          // 30,720 compact rows per batch
#define NSLICE (NB * ROWS)      // 61,440

#define SP 197                  // slab row stride; 197 % 32 == 5 (bank spread)
#define GUARD_LO 8
#define GUARD_HI 9
#define MAX_NZ 19               // max slab planes: 8 + 2 + 9
#define CHUNK_ROWS 64
#define CHUNKS_PER_B (ROWS / CHUNK_ROWS)   // 480
#define NCHUNK (NB * CHUNKS_PER_B)         // 960
#define TPB 256
#define GA (CHUNK_ROWS * 54)    // 3456 phase-A groups per chunk (x in [8,224))
#define GB (CHUNK_ROWS * 2)     // 128 phase-B groups per chunk (x in [0,8))

__device__ float g_bslice[NSLICE];      // compact [b][z*HH+y] = img[b][z][y][223]

__global__ __launch_bounds__(256) void extract_border_kernel(
    const float* __restrict__ img)
{
    int idx = blockIdx.x * blockDim.x + threadIdx.x;
    if (idx >= NSLICE) return;
    int b = idx / ROWS;
    int r = idx - b * ROWS;           // z*HH + y
    int z = r / HH;
    int y = r - z * HH;
    g_bslice[idx] = img[(size_t)b * NVOX + (size_t)z * HW + y * WW + (WW - 1)];
}

// general (non-border) trilinear sample for one voxel
__device__ __forceinline__ float sample_general(
    const float* __restrict__ im, float pxr,
    int y0, int z0, float fy, float fz)
{
    const float px = fmaxf(pxr, 0.0f);          // px < 223 on this path
    const float x0f = floorf(px);
    const float fx = px - x0f;
    const int x0 = (int)x0f;
    const int x1 = min(x0 + 1, WW - 1);
    const int y1 = min(y0 + 1, HH - 1);
    const int z1 = min(z0 + 1, DD - 1);

    const int zb0 = z0 * HW;
    const int zb1 = z1 * HW;
    const int yb0 = y0 * WW;
    const int yb1 = y1 * WW;

    const float c000 = __ldg(im + zb0 + yb0 + x0);
    const float c001 = __ldg(im + zb0 + yb0 + x1);
    const float c010 = __ldg(im + zb0 + yb1 + x0);
    const float c011 = __ldg(im + zb0 + yb1 + x1);
    const float c100 = __ldg(im + zb1 + yb0 + x0);
    const float c101 = __ldg(im + zb1 + yb0 + x1);
    const float c110 = __ldg(im + zb1 + yb1 + x0);
    const float c111 = __ldg(im + zb1 + yb1 + x1);

    const float c00 = c000 + (c001 - c000) * fx;
    const float c01 = c010 + (c011 - c010) * fx;
    const float c10 = c100 + (c101 - c100) * fx;
    const float c11 = c110 + (c111 - c110) * fx;
    const float c0 = c00 + (c01 - c00) * fy;
    const float c1 = c10 + (c11 - c10) * fy;
    return c0 + (c1 - c0) * fz;
}

// border-column bilinear: smem slab if z-range cached, else global compact slice
__device__ __forceinline__ float sample_border(
    const float* __restrict__ s_slab, const float* __restrict__ gs,
    int zs_lo, int zs_hi, int y0, int z0, float fy, float fz)
{
    const int y1 = min(y0 + 1, HH - 1);
    const int z1 = min(z0 + 1, DD - 1);
    float v00, v01, v10, v11;
    if (z0 >= zs_lo && z1 <= zs_hi) {
        const int r0 = (z0 - zs_lo) * SP + y0;
        const int r1 = (z1 - zs_lo) * SP + y0;
        v00 = s_slab[r0];
        v01 = s_slab[r0 + (y1 - y0)];
        v10 = s_slab[r1];
        v11 = s_slab[r1 + (y1 - y0)];
    } else {                                   // Gaussian tail: ~never taken
        v00 = __ldg(gs + z0 * HH + y0);
        v01 = __ldg(gs + z0 * HH + y1);
        v10 = __ldg(gs + z1 * HH + y0);
        v11 = __ldg(gs + z1 * HH + y1);
    }
    const float c0 = v00 + (v01 - v00) * fy;
    const float c1 = v10 + (v11 - v10) * fy;
    return c0 + (c1 - c0) * fz;
}

__global__ __launch_bounds__(TPB, 5) void st3d_kernel(
    const float* __restrict__ img,
    const float* __restrict__ flow,
    float* __restrict__ out)
{
    __shared__ float s_slab[MAX_NZ * SP];   // 14,972 B

    const int tid = threadIdx.x;
    const int q = blockIdx.x;               // chunk id
    const int b = (q >= CHUNKS_PER_B) ? 1 : 0;
    const int r0 = (q - b * CHUNKS_PER_B) * CHUNK_ROWS;   // first compact row

    const int z_lo = r0 / HH;
    const int z_hi = (r0 + CHUNK_ROWS - 1) / HH;
    const int zs_lo = max(z_lo - GUARD_LO, 0);
    const int zs_hi = min(z_hi + GUARD_HI, DD - 1);
    const int nz = zs_hi - zs_lo + 1;       // <= 19

    const float* gs = g_bslice + b * ROWS;  // compact slice for this batch

    // ---- fill smem slab ----
    {
        const float* src = gs + zs_lo * HH;
        for (int idx = tid; idx < nz * HH; idx += TPB) {
            const int zz = idx / HH;
            const int yy = idx - zz * HH;
            s_slab[zz * SP + yy] = __ldg(src + idx);
        }
    }
    __syncthreads();

    const float* fb = flow + (size_t)b * 3 * NVOX;
    const float* im = img + (size_t)b * NVOX;
    float* ob = out + (size_t)b * NVOX;

    // ================= Phase A: x in [8,224) — warp-uniform fast path =========
    {
        int g = tid;
        bool valid = (g < GA);
        float4 nf0, nf1, nf2;
        int ni = 0;
        if (valid) {
            const int row = r0 + g / 54;
            ni = row * WW + 8 + (g % 54) * 4;
            nf0 = __ldcs(reinterpret_cast<const float4*>(fb + ni));
            nf1 = __ldcs(reinterpret_cast<const float4*>(fb + NVOX + ni));
            nf2 = __ldcs(reinterpret_cast<const float4*>(fb + 2 * NVOX + ni));
        }

        while (valid) {
            const int i = ni;
            const float4 f0 = nf0, f1 = nf1, f2 = nf2;

            const int gn = g + TPB;
            const bool nvalid = (gn < GA);
            if (nvalid) {
                const int rown = r0 + gn / 54;
                ni = rown * WW + 8 + (gn % 54) * 4;
                nf0 = __ldcs(reinterpret_cast<const float4*>(fb + ni));
                nf1 = __ldcs(reinterpret_cast<const float4*>(fb + NVOX + ni));
                nf2 = __ldcs(reinterpret_cast<const float4*>(fb + 2 * NVOX + ni));
            }

            const int z = i / HW;
            const int rem = i - z * HW;
            const int y = rem / WW;
            const int x = rem - y * WW;

            const float f0a[4] = {f0.x, f0.y, f0.z, f0.w};
            const float f1a[4] = {f1.x, f1.y, f1.z, f1.w};
            const float f2a[4] = {f2.x, f2.y, f2.z, f2.w};

            float oa[4];
            #pragma unroll
            for (int k = 0; k < 4; ++k) {
                const float pxr = ((float)(x + k) + f0a[k] + 1.0f) * 111.5f;

                float py = (float)y + f1a[k];
                float pz = (float)z + f2a[k];
                py = fminf(fmaxf(py, 0.0f), (float)(HH - 1));
                pz = fminf(fmaxf(pz, 0.0f), (float)(DD - 1));

                const float y0f = floorf(py);
                const float z0f = floorf(pz);
                const float fy = py - y0f;
                const float fz = pz - z0f;
                const int y0 = (int)y0f;
                const int z0 = (int)z0f;

                if (pxr >= (float)(WW - 1)) {   // uniform-true for x >= 8
                    oa[k] = sample_border(s_slab, gs, zs_lo, zs_hi, y0, z0, fy, fz);
                } else {
                    oa[k] = sample_general(im, pxr, y0, z0, fy, fz);
                }
            }

            __stcs(reinterpret_cast<float4*>(ob + i),
                   make_float4(oa[0], oa[1], oa[2], oa[3]));

            g = gn;
            valid = nvalid;
        }
    }

    // ================= Phase B: x in [0,8) — mixed path (3.6% of voxels) ======
    for (int g = tid; g < GB; g += TPB) {
        const int row = r0 + (g >> 1);
        const int gi = g & 1;
        const int i = row * WW + gi * 4;
        const int z = row / HH;
        const int y = row - z * HH;
        const int x = gi * 4;

        const float4 f0 = __ldcs(reinterpret_cast<const float4*>(fb + i));
        const float4 f1 = __ldcs(reinterpret_cast<const float4*>(fb + NVOX + i));
        const float4 f2 = __ldcs(reinterpret_cast<const float4*>(fb + 2 * NVOX + i));

        const float f0a[4] = {f0.x, f0.y, f0.z, f0.w};
        const float f1a[4] = {f1.x, f1.y, f1.z, f1.w};
        const float f2a[4] = {f2.x, f2.y, f2.z, f2.w};

        float oa[4];
        #pragma unroll
        for (int k = 0; k < 4; ++k) {
            const float pxr = ((float)(x + k) + f0a[k] + 1.0f) * 111.5f;

            float py = (float)y + f1a[k];
            float pz = (float)z + f2a[k];
            py = fminf(fmaxf(py, 0.0f), (float)(HH - 1));
            pz = fminf(fmaxf(pz, 0.0f), (float)(DD - 1));

            const float y0f = floorf(py);
            const float z0f = floorf(pz);
            const float fy = py - y0f;
            const float fz = pz - z0f;
            const int y0 = (int)y0f;
            const int z0 = (int)z0f;

            if (pxr >= (float)(WW - 1)) {
                oa[k] = sample_border(s_slab, gs, zs_lo, zs_hi, y0, z0, fy, fz);
            } else {
                oa[k] = sample_general(im, pxr, y0, z0, fy, fz);
            }
        }

        __stcs(reinterpret_cast<float4*>(ob + i),
               make_float4(oa[0], oa[1], oa[2], oa[3]));
    }
}

extern "C" void kernel_launch(void* const* d_in, const int* in_sizes, int n_in,
                              void* d_out, int out_size)
{
    const float* img  = (const float*)d_in[0];
    const float* flow = (const float*)d_in[1];
    float* out = (float*)d_out;

    extract_border_kernel<<<(NSLICE + 255) / 256, 256>>>(img);
    st3d_kernel<<<NCHUNK, TPB>>>(img, flow, out);
}

// round 13
// speedup vs baseline: 1.0158x; 1.0158x over previous
#include <cuda_runtime.h>
#include <cuda_bf16.h>
#include <cstdint>

// SpatialTransformer: 3D trilinear grid-sample, border padding, align_corners=True.
// img [2,1,160,192,224], flow [2,3,160,192,224], out [2,1,160,192,224].
//
// px = (x+flow0+1)*111.5 clamps to 223 (fx=0) for essentially all x>=8 ->
// bilinear on the x=223 slice, held ENTIRELY in shared memory (160 x 197-padded
// floats, 126 KB; 197%32==5 spreads the warp's (z0,y0) patch across banks).
// Phase A: x in [8,224) warp-uniform fast path (4 LDS + 6 FFMA).
// Phase B: x in [0,8) mixed path (3.6% of voxels).
// R13: flow is streamed through a per-thread cp.async double-buffered smem ring
// (2 stages x 3 ch x 1024 x 16B = 96 KB) -> 2 iterations of flow bytes in
// flight per thread with ZERO register cost and no CTA barriers.

#define DD 160
#define HH 192
#define WW 224
#define HW (HH * WW)
#define NVOX (DD * HH * WW)     // 6,881,280
#define NB 2
#define ROWS (DD * HH)          // 30,720
#define NSLICE (NB * ROWS)      // 61,440

#define SP 197                  // padded smem row stride; 197 % 32 == 5
#define SLICE_FLOATS (DD * SP)  // 31,520
#define FBUF_FLOATS (2 * 3 * 1024 * 4)  // 24,576 floats = 96 KB
#define SMEM_TOTAL_BYTES ((SLICE_FLOATS + FBUF_FLOATS) * 4)   // 224,384

#define CTAS_PER_B 74
#define GRID_MAIN (2 * CTAS_PER_B)      // 148
#define TPB 1024
#define GSTRIDE (CTAS_PER_B * TPB)      // 75,776

#define MAIN_G (ROWS * 54)      // 1,658,880 groups (x in [8,224), 4 voxels each)
#define EDGE_G (ROWS * 2)       // 61,440 groups (x in [0,8))

__device__ float g_bslice[NSLICE];      // compact [b][z*HH+y] = img[b][z][y][223]

__global__ __launch_bounds__(256) void extract_border_kernel(
    const float* __restrict__ img)
{
    int idx = blockIdx.x * blockDim.x + threadIdx.x;
    if (idx >= NSLICE) return;
    int b = idx / ROWS;
    int r = idx - b * ROWS;           // z*HH + y
    int z = r / HH;
    int y = r - z * HH;
    g_bslice[idx] = img[(size_t)b * NVOX + (size_t)z * HW + y * WW + (WW - 1)];
}

__device__ __forceinline__ uint32_t smem_u32(const void* p) {
    uint32_t a;
    asm("{ .reg .u64 t; cvta.to.shared.u64 t, %1; cvt.u32.u64 %0, t; }"
        : "=r"(a) : "l"(p));
    return a;
}
__device__ __forceinline__ void cp_async16(uint32_t dst, const float* src) {
    asm volatile("cp.async.cg.shared.global [%0], [%1], 16;"
                 :: "r"(dst), "l"(src) : "memory");
}
#define CP_COMMIT() asm volatile("cp.async.commit_group;" ::: "memory")
#define CP_WAIT1()  asm volatile("cp.async.wait_group 1;" ::: "memory")

// general (non-border) trilinear sample for one voxel
__device__ __forceinline__ float sample_general(
    const float* __restrict__ im, float pxr,
    int y0, int z0, float fy, float fz)
{
    const float px = fmaxf(pxr, 0.0f);          // px < 223 on this path
    const float x0f = floorf(px);
    const float fx = px - x0f;
    const int x0 = (int)x0f;
    const int x1 = min(x0 + 1, WW - 1);
    const int y1 = min(y0 + 1, HH - 1);
    const int z1 = min(z0 + 1, DD - 1);

    const int zb0 = z0 * HW;
    const int zb1 = z1 * HW;
    const int yb0 = y0 * WW;
    const int yb1 = y1 * WW;

    const float c000 = __ldg(im + zb0 + yb0 + x0);
    const float c001 = __ldg(im + zb0 + yb0 + x1);
    const float c010 = __ldg(im + zb0 + yb1 + x0);
    const float c011 = __ldg(im + zb0 + yb1 + x1);
    const float c100 = __ldg(im + zb1 + yb0 + x0);
    const float c101 = __ldg(im + zb1 + yb0 + x1);
    const float c110 = __ldg(im + zb1 + yb1 + x0);
    const float c111 = __ldg(im + zb1 + yb1 + x1);

    const float c00 = c000 + (c001 - c000) * fx;
    const float c01 = c010 + (c011 - c010) * fx;
    const float c10 = c100 + (c101 - c100) * fx;
    const float c11 = c110 + (c111 - c110) * fx;
    const float c0 = c00 + (c01 - c00) * fy;
    const float c1 = c10 + (c11 - c10) * fy;
    return c0 + (c1 - c0) * fz;
}

// issue one pipeline stage (3 x 16B cp.async) for group gj; always commits
__device__ __forceinline__ void issue_stage(
    const float* __restrict__ fb, uint32_t fbase, int tid, int stage, int gj)
{
    if (gj < MAIN_G) {
        const int row = gj / 54;
        const int ii = row * WW + 8 + (gj - row * 54) * 4;
        const float* p = fb + ii;
        const uint32_t d = fbase + (uint32_t)(stage * 3 * 1024 + tid) * 16u;
        cp_async16(d,                 p);
        cp_async16(d + 1024u * 16u,   p + NVOX);
        cp_async16(d + 2048u * 16u,   p + 2 * NVOX);
    }
    CP_COMMIT();
}

__global__ __launch_bounds__(TPB, 1) void st3d_kernel(
    const float* __restrict__ img,
    const float* __restrict__ flow,
    float* __restrict__ out)
{
    extern __shared__ float smem[];
    float* s_slice = smem;                           // [DD][SP]
    float4* s_fbuf = (float4*)(smem + SLICE_FLOATS); // [2][3][1024]

    const int tid = threadIdx.x;
    const int cta = blockIdx.x;
    const int b = (cta >= CTAS_PER_B) ? 1 : 0;
    const int c = cta - b * CTAS_PER_B;

    // ---- fill smem slice (row-padded) from compact global slice ----
    {
        const float* src = g_bslice + b * ROWS;
        for (int idx = tid; idx < ROWS; idx += TPB) {
            const int z = idx / HH;
            const int y = idx - z * HH;
            s_slice[z * SP + y] = __ldg(src + idx);
        }
    }
    __syncthreads();

    const float* fb = flow + (size_t)b * 3 * NVOX;
    const float* im = img + (size_t)b * NVOX;
    float* ob = out + (size_t)b * NVOX;
    const uint32_t fbase = smem_u32(s_fbuf);

    // ================= Phase A: x in [8,224) — warp-uniform fast path =========
    {
        const int g0 = c * TPB + tid;    // always < GSTRIDE <= MAIN_G
        issue_stage(fb, fbase, tid, 0, g0);
        issue_stage(fb, fbase, tid, 1, g0 + GSTRIDE);

        int gj = g0;
        int j = 0;
        while (gj < MAIN_G) {
            const int stage = j & 1;
            CP_WAIT1();                  // stage buffers for iteration j ready

            const float4 f0 = s_fbuf[stage * 3 * 1024 + tid];
            const float4 f1 = s_fbuf[stage * 3 * 1024 + 1024 + tid];
            const float4 f2 = s_fbuf[stage * 3 * 1024 + 2048 + tid];

            // refill this stage for iteration j+2 (always commits)
            issue_stage(fb, fbase, tid, stage, gj + 2 * GSTRIDE);

            const int row = gj / 54;
            const int i = row * WW + 8 + (gj - row * 54) * 4;
            const int z = row / HH;
            const int y = row - z * HH;
            const int x = i - row * WW;

            const float f0a[4] = {f0.x, f0.y, f0.z, f0.w};
            const float f1a[4] = {f1.x, f1.y, f1.z, f1.w};
            const float f2a[4] = {f2.x, f2.y, f2.z, f2.w};

            float oa[4];
            #pragma unroll
            for (int k = 0; k < 4; ++k) {
                const float pxr = ((float)(x + k) + f0a[k] + 1.0f) * 111.5f;

                float py = (float)y + f1a[k];
                float pz = (float)z + f2a[k];
                py = fminf(fmaxf(py, 0.0f), (float)(HH - 1));
                pz = fminf(fmaxf(pz, 0.0f), (float)(DD - 1));

                const float y0f = floorf(py);
                const float z0f = floorf(pz);
                const float fy = py - y0f;
                const float fz = pz - z0f;
                const int y0 = (int)y0f;
                const int z0 = (int)z0f;

                if (pxr >= (float)(WW - 1)) {   // uniform-true for x >= 8
                    const int y1 = min(y0 + 1, HH - 1);
                    const int z1 = min(z0 + 1, DD - 1);
                    const int r0 = z0 * SP;
                    const int r1 = z1 * SP;
                    const float v00 = s_slice[r0 + y0];
                    const float v01 = s_slice[r0 + y1];
                    const float v10 = s_slice[r1 + y0];
                    const float v11 = s_slice[r1 + y1];
                    const float c0 = v00 + (v01 - v00) * fy;
                    const float c1 = v10 + (v11 - v10) * fy;
                    oa[k] = c0 + (c1 - c0) * fz;
                } else {
                    oa[k] = sample_general(im, pxr, y0, z0, fy, fz);
                }
            }

            __stcs(reinterpret_cast<float4*>(ob + i),
                   make_float4(oa[0], oa[1], oa[2], oa[3]));

            gj += GSTRIDE;
            ++j;
        }
    }

    // ================= Phase B: x in [0,8) — mixed path (3.6% of voxels) ======
    for (int g = c * TPB + tid; g < EDGE_G; g += GSTRIDE) {
        const int row = g >> 1;
        const int gi = g & 1;
        const int i = row * WW + gi * 4;
        const int z = row / HH;
        const int y = row - z * HH;
        const int x = gi * 4;

        const float4 f0 = __ldcs(reinterpret_cast<const float4*>(fb + i));
        const float4 f1 = __ldcs(reinterpret_cast<const float4*>(fb + NVOX + i));
        const float4 f2 = __ldcs(reinterpret_cast<const float4*>(fb + 2 * NVOX + i));

        const float f0a[4] = {f0.x, f0.y, f0.z, f0.w};
        const float f1a[4] = {f1.x, f1.y, f1.z, f1.w};
        const float f2a[4] = {f2.x, f2.y, f2.z, f2.w};

        float oa[4];
        #pragma unroll
        for (int k = 0; k < 4; ++k) {
            const float pxr = ((float)(x + k) + f0a[k] + 1.0f) * 111.5f;

            float py = (float)y + f1a[k];
            float pz = (float)z + f2a[k];
            py = fminf(fmaxf(py, 0.0f), (float)(HH - 1));
            pz = fminf(fmaxf(pz, 0.0f), (float)(DD - 1));

            const float y0f = floorf(py);
            const float z0f = floorf(pz);
            const float fy = py - y0f;
            const float fz = pz - z0f;
            const int y0 = (int)y0f;
            const int z0 = (int)z0f;

            if (pxr >= (float)(WW - 1)) {
                const int y1 = min(y0 + 1, HH - 1);
                const int z1 = min(z0 + 1, DD - 1);
                const int r0 = z0 * SP;
                const int r1 = z1 * SP;
                const float v00 = s_slice[r0 + y0];
                const float v01 = s_slice[r0 + y1];
                const float v10 = s_slice[r1 + y0];
                const float v11 = s_slice[r1 + y1];
                const float c0 = v00 + (v01 - v00) * fy;
                const float c1 = v10 + (v11 - v10) * fy;
                oa[k] = c0 + (c1 - c0) * fz;
            } else {
                oa[k] = sample_general(im, pxr, y0, z0, fy, fz);
            }
        }

        __stcs(reinterpret_cast<float4*>(ob + i),
               make_float4(oa[0], oa[1], oa[2], oa[3]));
    }
}

extern "C" void kernel_launch(void* const* d_in, const int* in_sizes, int n_in,
                              void* d_out, int out_size)
{
    const float* img  = (const float*)d_in[0];
    const float* flow = (const float*)d_in[1];
    float* out = (float*)d_out;

    cudaFuncSetAttribute(st3d_kernel,
                         cudaFuncAttributeMaxDynamicSharedMemorySize,
                         SMEM_TOTAL_BYTES);

    extract_border_kernel<<<(NSLICE + 255) / 256, 256>>>(img);
    st3d_kernel<<<GRID_MAIN, TPB, SMEM_TOTAL_BYTES>>>(img, flow, out);
}

// round 14
// speedup vs baseline: 1.3950x; 1.3733x over previous
#include <cuda_runtime.h>
#include <cuda_bf16.h>

// SpatialTransformer: 3D trilinear grid-sample, border padding, align_corners=True.
// img [2,1,160,192,224], flow [2,3,160,192,224], out [2,1,160,192,224].
//
// px = (x+flow0+1)*111.5 clamps to 223 (fx=0) for essentially all x>=8 ->
// bilinear on the x=223 slice, held ENTIRELY in shared memory (160 x 197-padded
// floats, 126 KB; 197%32==5 spreads the warp's (z0,y0) patch across banks).
// Phase A: x in [8,224) warp-uniform fast path (4 LDS + 6 FFMA), 8 voxels per
// thread with 6 FRONT-BATCHED float4 flow loads (deep MLP, no prefetch regs).
// Phase B: x in [0,8) mixed path (3.6% of voxels).

#define DD 160
#define HH 192
#define WW 224
#define HW (HH * WW)
#define NVOX (DD * HH * WW)     // 6,881,280
#define NB 2
#define ROWS (DD * HH)          // 30,720
#define NSLICE (NB * ROWS)      // 61,440

#define SP 197                  // padded smem row stride; 197 % 32 == 5
#define SLICE_BYTES (DD * SP * 4)       // 126,080

#define CTAS_PER_B 74
#define GRID_MAIN (2 * CTAS_PER_B)      // 148
#define TPB 1024
#define GSTRIDE (CTAS_PER_B * TPB)      // 75,776

#define MAIN_G8 (ROWS * 27)     // 829,440 groups of 8 voxels (x in [8,224))
#define EDGE_G (ROWS * 2)       // 61,440 groups of 4 voxels (x in [0,8))

__device__ float g_bslice[NSLICE];      // compact [b][z*HH+y] = img[b][z][y][223]

__global__ __launch_bounds__(256) void extract_border_kernel(
    const float* __restrict__ img)
{
    int idx = blockIdx.x * blockDim.x + threadIdx.x;
    if (idx >= NSLICE) return;
    int b = idx / ROWS;
    int r = idx - b * ROWS;           // z*HH + y
    int z = r / HH;
    int y = r - z * HH;
    g_bslice[idx] = img[(size_t)b * NVOX + (size_t)z * HW + y * WW + (WW - 1)];
}

// general (non-border) trilinear sample for one voxel
__device__ __forceinline__ float sample_general(
    const float* __restrict__ im, float pxr,
    int y0, int z0, float fy, float fz)
{
    const float px = fmaxf(pxr, 0.0f);          // px < 223 on this path
    const float x0f = floorf(px);
    const float fx = px - x0f;
    const int x0 = (int)x0f;
    const int x1 = min(x0 + 1, WW - 1);
    const int y1 = min(y0 + 1, HH - 1);
    const int z1 = min(z0 + 1, DD - 1);

    const int zb0 = z0 * HW;
    const int zb1 = z1 * HW;
    const int yb0 = y0 * WW;
    const int yb1 = y1 * WW;

    const float c000 = __ldg(im + zb0 + yb0 + x0);
    const float c001 = __ldg(im + zb0 + yb0 + x1);
    const float c010 = __ldg(im + zb0 + yb1 + x0);
    const float c011 = __ldg(im + zb0 + yb1 + x1);
    const float c100 = __ldg(im + zb1 + yb0 + x0);
    const float c101 = __ldg(im + zb1 + yb0 + x1);
    const float c110 = __ldg(im + zb1 + yb1 + x0);
    const float c111 = __ldg(im + zb1 + yb1 + x1);

    const float c00 = c000 + (c001 - c000) * fx;
    const float c01 = c010 + (c011 - c010) * fx;
    const float c10 = c100 + (c101 - c100) * fx;
    const float c11 = c110 + (c111 - c110) * fx;
    const float c0 = c00 + (c01 - c00) * fy;
    const float c1 = c10 + (c11 - c10) * fy;
    return c0 + (c1 - c0) * fz;
}

__global__ __launch_bounds__(TPB, 1) void st3d_kernel(
    const float* __restrict__ img,
    const float* __restrict__ flow,
    float* __restrict__ out)
{
    extern __shared__ float s_slice[];   // [DD][SP]

    const int tid = threadIdx.x;
    const int cta = blockIdx.x;
    const int b = (cta >= CTAS_PER_B) ? 1 : 0;
    const int c = cta - b * CTAS_PER_B;

    // ---- fill smem slice (row-padded) from compact global slice ----
    {
        const float* src = g_bslice + b * ROWS;
        for (int idx = tid; idx < ROWS; idx += TPB) {
            const int z = idx / HH;
            const int y = idx - z * HH;
            s_slice[z * SP + y] = __ldg(src + idx);
        }
    }
    __syncthreads();

    const float* fb = flow + (size_t)b * 3 * NVOX;
    const float* im = img + (size_t)b * NVOX;
    float* ob = out + (size_t)b * NVOX;

    // ====== Phase A: x in [8,224), 8 voxels/thread, warp-uniform fast path ====
    for (int g = c * TPB + tid; g < MAIN_G8; g += GSTRIDE) {
        const int row = g / 27;
        const int i = row * WW + 8 + (g - row * 27) * 8;   // 16B-aligned
        const int z = row / HH;
        const int y = row - z * HH;
        const int x = i - row * WW;

        // 6 front-batched streaming float4 loads (flow read exactly once)
        const float4 f0lo = __ldcs(reinterpret_cast<const float4*>(fb + i));
        const float4 f0hi = __ldcs(reinterpret_cast<const float4*>(fb + i + 4));
        const float4 f1lo = __ldcs(reinterpret_cast<const float4*>(fb + NVOX + i));
        const float4 f1hi = __ldcs(reinterpret_cast<const float4*>(fb + NVOX + i + 4));
        const float4 f2lo = __ldcs(reinterpret_cast<const float4*>(fb + 2 * NVOX + i));
        const float4 f2hi = __ldcs(reinterpret_cast<const float4*>(fb + 2 * NVOX + i + 4));

        const float f0a[8] = {f0lo.x, f0lo.y, f0lo.z, f0lo.w,
                              f0hi.x, f0hi.y, f0hi.z, f0hi.w};
        const float f1a[8] = {f1lo.x, f1lo.y, f1lo.z, f1lo.w,
                              f1hi.x, f1hi.y, f1hi.z, f1hi.w};
        const float f2a[8] = {f2lo.x, f2lo.y, f2lo.z, f2lo.w,
                              f2hi.x, f2hi.y, f2hi.z, f2hi.w};

        float oa[8];
        #pragma unroll
        for (int k = 0; k < 8; ++k) {
            const float pxr = ((float)(x + k) + f0a[k] + 1.0f) * 111.5f;

            float py = (float)y + f1a[k];
            float pz = (float)z + f2a[k];
            py = fminf(fmaxf(py, 0.0f), (float)(HH - 1));
            pz = fminf(fmaxf(pz, 0.0f), (float)(DD - 1));

            const float y0f = floorf(py);
            const float z0f = floorf(pz);
            const float fy = py - y0f;
            const float fz = pz - z0f;
            const int y0 = (int)y0f;
            const int z0 = (int)z0f;

            if (pxr >= (float)(WW - 1)) {   // uniform-true for x >= 8
                const int y1 = min(y0 + 1, HH - 1);
                const int z1 = min(z0 + 1, DD - 1);
                const int r0 = z0 * SP;
                const int r1 = z1 * SP;
                const float v00 = s_slice[r0 + y0];
                const float v01 = s_slice[r0 + y1];
                const float v10 = s_slice[r1 + y0];
                const float v11 = s_slice[r1 + y1];
                const float c0 = v00 + (v01 - v00) * fy;
                const float c1 = v10 + (v11 - v10) * fy;
                oa[k] = c0 + (c1 - c0) * fz;
            } else {
                oa[k] = sample_general(im, pxr, y0, z0, fy, fz);
            }
        }

        __stcs(reinterpret_cast<float4*>(ob + i),
               make_float4(oa[0], oa[1], oa[2], oa[3]));
        __stcs(reinterpret_cast<float4*>(ob + i + 4),
               make_float4(oa[4], oa[5], oa[6], oa[7]));
    }

    // ====== Phase B: x in [0,8) — mixed path (3.6% of voxels) ================
    for (int g = c * TPB + tid; g < EDGE_G; g += GSTRIDE) {
        const int row = g >> 1;
        const int gi = g & 1;
        const int i = row * WW + gi * 4;
        const int z = row / HH;
        const int y = row - z * HH;
        const int x = gi * 4;

        const float4 f0 = __ldcs(reinterpret_cast<const float4*>(fb + i));
        const float4 f1 = __ldcs(reinterpret_cast<const float4*>(fb + NVOX + i));
        const float4 f2 = __ldcs(reinterpret_cast<const float4*>(fb + 2 * NVOX + i));

        const float f0a[4] = {f0.x, f0.y, f0.z, f0.w};
        const float f1a[4] = {f1.x, f1.y, f1.z, f1.w};
        const float f2a[4] = {f2.x, f2.y, f2.z, f2.w};

        float oa[4];
        #pragma unroll
        for (int k = 0; k < 4; ++k) {
            const float pxr = ((float)(x + k) + f0a[k] + 1.0f) * 111.5f;

            float py = (float)y + f1a[k];
            float pz = (float)z + f2a[k];
            py = fminf(fmaxf(py, 0.0f), (float)(HH - 1));
            pz = fminf(fmaxf(pz, 0.0f), (float)(DD - 1));

            const float y0f = floorf(py);
            const float z0f = floorf(pz);
            const float fy = py - y0f;
            const float fz = pz - z0f;
            const int y0 = (int)y0f;
            const int z0 = (int)z0f;

            if (pxr >= (float)(WW - 1)) {
                const int y1 = min(y0 + 1, HH - 1);
                const int z1 = min(z0 + 1, DD - 1);
                const int r0 = z0 * SP;
                const int r1 = z1 * SP;
                const float v00 = s_slice[r0 + y0];
                const float v01 = s_slice[r0 + y1];
                const float v10 = s_slice[r1 + y0];
                const float v11 = s_slice[r1 + y1];
                const float c0 = v00 + (v01 - v00) * fy;
                const float c1 = v10 + (v11 - v10) * fy;
                oa[k] = c0 + (c1 - c0) * fz;
            } else {
                oa[k] = sample_general(im, pxr, y0, z0, fy, fz);
            }
        }

        __stcs(reinterpret_cast<float4*>(ob + i),
               make_float4(oa[0], oa[1], oa[2], oa[3]));
    }
}

extern "C" void kernel_launch(void* const* d_in, const int* in_sizes, int n_in,
                              void* d_out, int out_size)
{
    const float* img  = (const float*)d_in[0];
    const float* flow = (const float*)d_in[1];
    float* out = (float*)d_out;

    cudaFuncSetAttribute(st3d_kernel,
                         cudaFuncAttributeMaxDynamicSharedMemorySize, SLICE_BYTES);

    extract_border_kernel<<<(NSLICE + 255) / 256, 256>>>(img);
    st3d_kernel<<<GRID_MAIN, TPB, SLICE_BYTES>>>(img, flow, out);
}